// round 14
// baseline (speedup 1.0000x reference)
#include <cuda_runtime.h>
#include <cstdint>

#define T_LEN 2048
#define BATCH 32
#define HID   256
#define G3    768
#define SBLK  64            // 8 scan clusters x 8 CTAs
#define NTOT  128           // + 8 worker clusters (16 clusters, 8/die worst case)
#define NWORK 64
#define NTILE 8192

typedef unsigned long long ull;

// smem float offsets (scan CTA)
#define WB_OFF 0            // B weights [512 k][64 pc]            = 32768
#define HS_OFF 32768        // h slots [2][h0:256x4 | h1:256x4]    = 4096
#define RA_OFF 36864        // A partials [4 q][32 l][2 pc][4 r]   = 1024
#define RB_OFF 37888        // B partials                          = 1024
#define SG_OFF 38912        // gate staging [A:128 | B:128]        = 256
#define SMEM_FLOATS 39168
#define SMEM_BYTES  (SMEM_FLOATS * 4)

__device__ float g_X[(size_t)T_LEN * BATCH * 512];   // [m=t*32+b][c 512]
__device__ unsigned g_tcnt[T_LEN / 2];               // 8 tiles per row-pair per run
__device__ unsigned g_run;                           // epoch

// ---------------------------------------------------------------------------
__device__ __forceinline__ ull pack2(float v) {
    ull r; asm("mov.b64 %0, {%1, %1};" : "=l"(r) : "f"(v)); return r;
}
__device__ __forceinline__ void fma2(ull& d, ull a, ull b) {
    asm("fma.rn.f32x2 %0, %1, %2, %0;" : "+l"(d) : "l"(a), "l"(b));
}
__device__ __forceinline__ void unpack2(ull v, float& lo, float& hi) {
    asm("mov.b64 {%0, %1}, %2;" : "=f"(lo), "=f"(hi) : "l"(v));
}
__device__ __forceinline__ uint32_t smem_u32(const void* p) {
    uint32_t a;
    asm("{ .reg .u64 t; cvta.to.shared.u64 t, %1; cvt.u32.u64 %0, t; }"
        : "=r"(a) : "l"(p));
    return a;
}
__device__ __forceinline__ uint32_t mapa_u32(uint32_t local, uint32_t rank) {
    uint32_t r;
    asm("mapa.shared::cluster.u32 %0, %1, %2;" : "=r"(r) : "r"(local), "r"(rank));
    return r;
}
__device__ __forceinline__ void stv4_cluster(uint32_t a, float4 v) {
    asm volatile("st.shared::cluster.v4.f32 [%0], {%1,%2,%3,%4};"
                 :: "r"(a), "f"(v.x), "f"(v.y), "f"(v.z), "f"(v.w) : "memory");
}
__device__ __forceinline__ void poll_ge(const unsigned* addr, unsigned target) {
    unsigned v;
    do {
        asm volatile("ld.acquire.gpu.global.u32 %0, [%1];"
                     : "=r"(v) : "l"(addr) : "memory");
    } while ((int)(v - target) < 0);
}
__device__ __forceinline__ void cluster_bar() {
    asm volatile("barrier.cluster.arrive.aligned;" ::: "memory");
    asm volatile("barrier.cluster.wait.aligned;" ::: "memory");
}

// ---------------------------------------------------------------------------
// GEMM worker: grid-strided 64x64x256 tiles; g_X = input @ Wih0[:,:512] + b0
// ---------------------------------------------------------------------------
__device__ void gemm_worker(int wb, const float* __restrict__ A,
                            const float* __restrict__ W,
                            const float* __restrict__ bias,
                            float* smem, int Lmax)
{
    float (*As)[65] = (float(*)[65])smem;
    float (*Bs)[64] = (float(*)[64])(smem + 32 * 65);

    const int tid = threadIdx.x;
    const int tx  = tid & 15;
    const int ty  = tid >> 4;
    const int ar  = tid >> 2;
    const int ak  = (tid & 3) * 8;
    const int bk  = tid >> 3;
    const int bc  = (tid & 7) * 8;

    for (int n = wb; n < NTILE; n += NWORK) {
        const int bx = n >> 3;
        if (2 * bx >= Lmax) break;
        const int m0 = bx * 64;
        const int n0 = (n & 7) * 64;

        ull acc2[4][2];
#pragma unroll
        for (int i = 0; i < 4; i++) { acc2[i][0] = 0ull; acc2[i][1] = 0ull; }

        for (int k0 = 0; k0 < 256; k0 += 32) {
            float4 a0  = *(const float4*)&A[(size_t)(m0 + ar) * 256 + k0 + ak];
            float4 a1  = *(const float4*)&A[(size_t)(m0 + ar) * 256 + k0 + ak + 4];
            float4 b0v = *(const float4*)&W[(size_t)(k0 + bk) * G3 + n0 + bc];
            float4 b1v = *(const float4*)&W[(size_t)(k0 + bk) * G3 + n0 + bc + 4];

            As[ak + 0][ar] = a0.x; As[ak + 1][ar] = a0.y;
            As[ak + 2][ar] = a0.z; As[ak + 3][ar] = a0.w;
            As[ak + 4][ar] = a1.x; As[ak + 5][ar] = a1.y;
            As[ak + 6][ar] = a1.z; As[ak + 7][ar] = a1.w;
            *(float4*)&Bs[bk][bc]     = b0v;
            *(float4*)&Bs[bk][bc + 4] = b1v;
            __syncthreads();

#pragma unroll
            for (int kk = 0; kk < 32; kk++) {
                const ulonglong2 bq = *(const ulonglong2*)&Bs[kk][ty * 4];
#pragma unroll
                for (int ri = 0; ri < 4; ri++) {
                    const ull av = pack2(As[kk][tx * 4 + ri]);
                    fma2(acc2[ri][0], bq.x, av);
                    fma2(acc2[ri][1], bq.y, av);
                }
            }
            __syncthreads();
        }

        const float4 bv = *(const float4*)&bias[n0 + ty * 4];
#pragma unroll
        for (int ri = 0; ri < 4; ri++) {
            float4 v;
            unpack2(acc2[ri][0], v.x, v.y);
            unpack2(acc2[ri][1], v.z, v.w);
            v.x += bv.x; v.y += bv.y; v.z += bv.z; v.w += bv.w;
            *(float4*)&g_X[(size_t)(m0 + tx * 4 + ri) * 512 + n0 + ty * 4] = v;
        }

        __threadfence();
        __syncthreads();
        if (tid == 0) {
            asm volatile("red.release.gpu.global.add.u32 [%0], %1;"
                         :: "l"(&g_tcnt[bx]), "r"(1u) : "memory");
        }
    }
}

// ---------------------------------------------------------------------------
// ONE kernel, grid 128, cluster 8.
// blocks 0..63: scan. cluster = domain (4 batch rows); CTA owns 32 h-cols.
//   Round i: warps 4-7 compute h0(i) [i<Ld]; warps 0-3 compute h1(i-1) [i>=1];
//   reads slot (i-1)&1, writes (broadcasts) slot i&1; ONE cluster barrier/round.
// blocks 64..127: gemm workers (produce g_X, signal via g_tcnt).
// ---------------------------------------------------------------------------
__global__ __launch_bounds__(256, 1) __cluster_dims__(8, 1, 1)
void fused_all(
    const float* __restrict__ input,
    const float* __restrict__ Whh0,
    const float* __restrict__ Whh1,
    const float* __restrict__ Wih0,
    const float* __restrict__ Wih1,
    const float* __restrict__ b0,
    const float* __restrict__ b1,
    const int*   __restrict__ length,
    float* __restrict__ out1,
    float* __restrict__ hn)
{
    extern __shared__ float smem[];
    const int bid = blockIdx.x;
    const int tid = threadIdx.x;

    int Lmax = 0;
#pragma unroll 8
    for (int r = 0; r < BATCH; r++) Lmax = max(Lmax, length[r]);

    if (bid >= SBLK) {
        gemm_worker(bid - SBLK, input, Wih0, b0, smem, Lmax);
        return;
    }

    const int d    = bid >> 3;
    const int rank = bid & 7;
    const int c0   = rank * 32;
    const int dom4 = d * 4;

    int Ld = 0;
#pragma unroll
    for (int r = 0; r < 4; r++) Ld = max(Ld, length[dom4 + r]);

    const unsigned R  = *(volatile unsigned*)&g_run;
    const unsigned tb = R * 8u;

    // ---- init: zero h slots + staging; load B weights into smem ----
    for (int i = tid; i < 4096; i += 256) smem[HS_OFF + i] = 0.f;
    smem[SG_OFF + tid] = 0.f;
    for (int idx = tid; idx < 32768; idx += 256) {
        const int k = idx >> 6, pc = idx & 63;
        const int col = (pc < 32) ? (c0 + pc) : (256 + c0 + pc - 32);
        smem[WB_OFF + idx] = (k < 256) ? Whh1[(size_t)k * G3 + col]
                                       : Wih1[(size_t)(k - 256) * G3 + col];
    }
    __syncthreads();
    cluster_bar();

    const uint32_t sb = smem_u32(smem);
    uint32_t rbase[8];
#pragma unroll
    for (int p = 0; p < 8; p++) rbase[p] = mapa_u32(sb, p);

    const int wid  = tid >> 5;
    const int lane = tid & 31;
    // pre-col pair for dot threads: lane<16 -> h_pre cols, else t_pre cols
    const int col0 = (lane < 16) ? (c0 + 2 * lane) : (256 + c0 + 2 * lane - 32);

    // A-dot weights (warps 4-7 only): 2 pre-cols x 64 k in registers
    float wA0[64], wA1[64];
    if (wid >= 4) {
        const int q = wid - 4;
#pragma unroll
        for (int kk = 0; kk < 64; kk++) {
            wA0[kk] = Whh0[(size_t)(q * 64 + kk) * G3 + col0];
            wA1[kk] = Whh0[(size_t)(q * 64 + kk) * G3 + col0 + 1];
        }
    }

    // gate identities
    const int gj  = (tid & 127) >> 2;       // 0..31 local h-col
    const int gr  = tid & 3;                // batch row in domain
    const int glen = length[dom4 + gr];
    float gbh = 0.f, gbt = 0.f;
    if (tid >= 128) {                       // B gates live on warps 4-7
        gbh = b1[c0 + gj];
        gbt = b1[256 + c0 + gj];
    }
    float hcur = 0.f;                       // tid<128: h0 state; tid>=128: h1 state
    int rdy = 0;

    for (int i = 0; i <= Ld; i++) {
        const bool act0 = (i < Ld);
        const bool act1 = (i >= 1);
        const int rs = (i + 1) & 1;         // read slot ((i-1)&1)
        const int ws = i & 1;               // write slot

        float xh = 0.f, xt = 0.f;

        if (tid < 128) {
            // ---- A-gate prefetch (poll gemm + x-term), then B dot ----
            if (act0) {
                if ((i >> 1) >= rdy) {
                    poll_ge(&g_tcnt[i >> 1], tb + 8u);
                    rdy = (i >> 1) + 1;
                }
                const size_t m = (size_t)i * BATCH + dom4 + gr;
                xh = __ldg(&g_X[m * 512 + c0 + gj]);
                xt = __ldg(&g_X[m * 512 + 256 + c0 + gj]);
            }
            if (act1) {
                const int q = wid;          // 0..3 k-quarter of 512
                const float* hbase = smem + HS_OFF + rs * 2048
                                   + ((q < 2) ? 1024 + q * 512 : (q - 2) * 512);
                const float* wb = smem + WB_OFF + q * 128 * 64;
                ull a00 = 0ull, a01 = 0ull, a10 = 0ull, a11 = 0ull;
#pragma unroll 16
                for (int kk = 0; kk < 128; kk++) {
                    const ulonglong2 hv = *(const ulonglong2*)&hbase[kk * 4];
                    const float2 wv = *(const float2*)&wb[kk * 64 + 2 * lane];
                    const ull w0 = pack2(wv.x), w1 = pack2(wv.y);
                    fma2(a00, hv.x, w0); fma2(a01, hv.y, w0);
                    fma2(a10, hv.x, w1); fma2(a11, hv.y, w1);
                }
                ulonglong2 s0; s0.x = a00; s0.y = a01;
                ulonglong2 s1; s1.x = a10; s1.y = a11;
                *(ulonglong2*)&smem[RB_OFF + ((q * 32 + lane) * 2 + 0) * 4] = s0;
                *(ulonglong2*)&smem[RB_OFF + ((q * 32 + lane) * 2 + 1) * 4] = s1;
            }
        } else {
            // ---- A dot (layer 0, K=256) ----
            if (act0) {
                const int q = wid - 4;
                const float* hbase = smem + HS_OFF + rs * 2048 + q * 256;
                ull a00 = 0ull, a01 = 0ull, a10 = 0ull, a11 = 0ull;
#pragma unroll
                for (int kk = 0; kk < 64; kk++) {
                    const ulonglong2 hv = *(const ulonglong2*)&hbase[kk * 4];
                    const ull w0 = pack2(wA0[kk]), w1 = pack2(wA1[kk]);
                    fma2(a00, hv.x, w0); fma2(a01, hv.y, w0);
                    fma2(a10, hv.x, w1); fma2(a11, hv.y, w1);
                }
                ulonglong2 s0; s0.x = a00; s0.y = a01;
                ulonglong2 s1; s1.x = a10; s1.y = a11;
                *(ulonglong2*)&smem[RA_OFF + ((q * 32 + lane) * 2 + 0) * 4] = s0;
                *(ulonglong2*)&smem[RA_OFF + ((q * 32 + lane) * 2 + 1) * 4] = s1;
            }
        }
        __syncthreads();

        // ---- gates ----
        if (tid < 128) {
            if (act0) {                      // A gates: h0(i)
                float sh = 0.f, st = 0.f;
#pragma unroll
                for (int q = 0; q < 4; q++) {
                    sh += smem[RA_OFF + ((q * 32 + (gj >> 1)) * 2 + (gj & 1)) * 4 + gr];
                    st += smem[RA_OFF + ((q * 32 + 16 + (gj >> 1)) * 2 + (gj & 1)) * 4 + gr];
                }
                const float ph = sh + xh, pt = st + xt;
                const float tg = 1.f / (1.f + __expf(-pt));
                const float cg = 1.f / (1.f + __expf(-tg));   // bug-faithful
                const float sv = tanhf(ph) * tg + hcur * cg;
                hcur = (i < glen) ? sv : hcur;
                smem[SG_OFF + tid] = hcur;
            }
        } else {
            if (act1) {                      // B gates: h1(i-1)
                float sh = 0.f, st = 0.f;
#pragma unroll
                for (int q = 0; q < 4; q++) {
                    sh += smem[RB_OFF + ((q * 32 + (gj >> 1)) * 2 + (gj & 1)) * 4 + gr];
                    st += smem[RB_OFF + ((q * 32 + 16 + (gj >> 1)) * 2 + (gj & 1)) * 4 + gr];
                }
                const float ph = sh + gbh, pt = st + gbt;
                const float tg = 1.f / (1.f + __expf(-pt));
                const float cg = 1.f / (1.f + __expf(-tg));   // bug-faithful
                const float sv = tanhf(ph) * tg + hcur * cg;
                hcur = ((i - 1) < glen) ? sv : hcur;
                smem[SG_OFF + tid] = hcur;
                out1[((size_t)(i - 1) * BATCH + dom4 + gr) * HID + c0 + gj] = hcur;
            }
        }
        __syncthreads();

        // ---- broadcast own 32 cols (both layers) into all 8 peers' slot ws ----
        {
            const int idx = tid * 2;         // layer = idx>>8, j = (idx>>3)&31
            const int layer = idx >> 8;
            const int j = (idx >> 3) & 31;
            const float4 v = *(const float4*)&smem[SG_OFF + layer * 128 + j * 4];
            const uint32_t doff = (uint32_t)(HS_OFF + ws * 2048 + layer * 1024
                                             + (c0 + j) * 4) * 4;
            stv4_cluster(rbase[idx & 7] + doff, v);
            stv4_cluster(rbase[(idx & 7) ^ 1] + doff, v);
        }
        cluster_bar();                       // release stores / acquire for next read
    }

    // ---- epilogue: hn + frozen-tail fill ----
    if (tid < 128) {
        hn[(dom4 + gr) * HID + c0 + gj] = hcur;               // layer 0
    } else {
        hn[BATCH * HID + (dom4 + gr) * HID + c0 + gj] = hcur; // layer 1
        smem[RB_OFF + gr * 32 + gj] = hcur;                   // transpose for fill
    }
    __syncthreads();
    {
        const int nf4 = (T_LEN - Ld) * 32;   // units: (t, rr(4), j4(8)) float4
        for (int idx = tid; idx < nf4; idx += 256) {
            const int t  = Ld + (idx >> 5);
            const int rr = (idx >> 3) & 3;
            const int j4 = idx & 7;
            *(float4*)&out1[((size_t)t * BATCH + dom4 + rr) * HID + c0 + j4 * 4] =
                *(const float4*)&smem[RB_OFF + rr * 32 + j4 * 4];
        }
    }
    if (bid == 0 && tid == 0) *(volatile unsigned*)&g_run = R + 1u;
}

// ---------------------------------------------------------------------------
extern "C" void kernel_launch(void* const* d_in, const int* in_sizes, int n_in,
                              void* d_out, int out_size) {
    const float* input  = (const float*)d_in[0];
    const int*   length = (const int*)d_in[1];
    const float* Wih0   = (const float*)d_in[2];
    const float* Whh0   = (const float*)d_in[3];
    const float* b0     = (const float*)d_in[4];
    const float* Wih1   = (const float*)d_in[5];
    const float* Whh1   = (const float*)d_in[6];
    const float* b1     = (const float*)d_in[7];

    float* out1 = (float*)d_out;
    float* hn   = (float*)d_out + (size_t)T_LEN * BATCH * HID;

    static bool attr_set = false;
    if (!attr_set) {
        cudaFuncSetAttribute(fused_all, cudaFuncAttributeMaxDynamicSharedMemorySize,
                             SMEM_BYTES);
        attr_set = true;
    }

    fused_all<<<NTOT, 256, SMEM_BYTES>>>(
        input, Whh0, Whh1, Wih0, Wih1, b0, b1, length, out1, hn);
}